// round 13
// baseline (speedup 1.0000x reference)
#include <cuda_runtime.h>
#include <cuda_fp16.h>
#include <stdint.h>

#define BATCH 16
#define SEQ 256
#define DIM 256
#define MAT 65536
#define NTOT 1048576
#define ABAR 0.042323627f   // 1/(1+sqrt(512))

// ---------------------------------------------------------------------------
// Device-global scratch (no atomics: fixed-slot partial sums)
// ---------------------------------------------------------------------------
__device__ float g_x1att[NTOT];
__device__ float g_x2att[NTOT];
__device__ float g_n1[BATCH*SEQ];
__device__ float g_n2[BATCH*SEQ];
__device__ float g_corr[DIM];  // ABAR*rowsum(W)+bias
__device__ __half g_x1h[NTOT];
__device__ __half g_x2h[NTOT];
__device__ __half g_Wh[SEQ*DIM];
// partial BN stats
__device__ float g_p1s[256], g_p1q[256];   // x1 (ch0), one per prep block
__device__ float g_p2s[256], g_p2q[256];   // x2 (ch2)
__device__ float g_pa1s[32], g_pa1q[32];   // x1_att (ch1), one per att CTA
__device__ float g_pa3s[32], g_pa3q[32];   // x2_att (ch3)

// ---------------------------------------------------------------------------
// Portable-ISA helpers (sm_80+)
// ---------------------------------------------------------------------------
__device__ __forceinline__ uint32_t smem_to_u32(const void* p) {
    uint32_t a;
    asm("{ .reg .u64 t; cvta.to.shared.u64 t, %1; cvt.u32.u64 %0, t; }" : "=r"(a) : "l"(p));
    return a;
}
__device__ __forceinline__ void ldsm4(uint32_t* r, uint32_t addr) {
    asm volatile("ldmatrix.sync.aligned.m8n8.x4.shared.b16 {%0,%1,%2,%3}, [%4];"
                 : "=r"(r[0]), "=r"(r[1]), "=r"(r[2]), "=r"(r[3]) : "r"(addr));
}
__device__ __forceinline__ void mma_fp16(float* c, const uint32_t* a, const uint32_t* b) {
    asm volatile("mma.sync.aligned.m16n8k16.row.col.f32.f16.f16.f32 "
                 "{%0,%1,%2,%3}, {%4,%5,%6,%7}, {%8,%9}, {%0,%1,%2,%3};"
                 : "+f"(c[0]), "+f"(c[1]), "+f"(c[2]), "+f"(c[3])
                 : "r"(a[0]), "r"(a[1]), "r"(a[2]), "r"(a[3]), "r"(b[0]), "r"(b[1]));
}
__device__ __forceinline__ void cp16(uint32_t saddr, const void* g) {
    asm volatile("cp.async.cg.shared.global [%0], [%1], 16;" :: "r"(saddr), "l"(g));
}
#define CP_COMMIT() asm volatile("cp.async.commit_group;" ::: "memory")
#define CP_WAIT1()  asm volatile("cp.async.wait_group 1;" ::: "memory")
#define CP_WAIT0()  asm volatile("cp.async.wait_group 0;" ::: "memory")

// SMEM geometry for the fused kernel (128-row blocks)
#define PR 528                  // pitch of 256-half rows (33x16B, conflict-free)
#define PB 144                  // pitch of 64-half rows
#define BTILE (256 * PB)        // 36864: one B chunk [256 n][64 k]
#define OFF_SNC   0             // 256 floats
#define OFF_SNR   1024          // 128 floats
#define OFF_CORR  1536          // 256 floats
#define OFF_STAT  2560          // 32 floats
#define OFF_SR    2688          // 128 x PR = 67584
#define OFF_SAT   70272         // 128 x PR = 67584
#define OFF_SD    137856        // 2 x BTILE = 73728
#define F_SMEM    211584

// ---------------------------------------------------------------------------
// k_prep: blocks [0,256) x1: 16 rows each, 2 rows/warp (MLP4, interleaved
//   reductions).  [256,512) x2.  [512,576) W fp16.  [576,608) corr.
// ---------------------------------------------------------------------------
__global__ void __launch_bounds__(256) k_prep(const float* __restrict__ x1,
                                              const float* __restrict__ x2,
                                              const float* __restrict__ W,
                                              const float* __restrict__ bias) {
    int blk = blockIdx.x;
    int t = threadIdx.x;
    int warp = t >> 5, lane = t & 31;
    if (blk >= 576) {   // corr rows
        int o = (blk - 576) * 8 + warp;
        float s = 0.f;
#pragma unroll
        for (int c = 0; c < 8; c++) s += W[o * SEQ + lane + c * 32];
#pragma unroll
        for (int off = 16; off; off >>= 1) s += __shfl_xor_sync(0xffffffffu, s, off);
        if (lane == 0) g_corr[o] = ABAR * s + bias[o];
        return;
    }
    if (blk >= 512) {   // W fp16 (vectorized)
        int base = (blk - 512) * 1024 + t * 4;
        float4 v = *(const float4*)&W[base];
        __half2 h0 = __floats2half2_rn(v.x, v.y);
        __half2 h1 = __floats2half2_rn(v.z, v.w);
        *(uint2*)&g_Wh[base] = make_uint2(*(uint32_t*)&h0, *(uint32_t*)&h1);
        return;
    }
    const float* X;
    float* Nrm;
    __half* Xh;
    float* Ps;
    float* Pq;
    if (blk < 256) { X = x1; Nrm = g_n1; Xh = g_x1h; Ps = g_p1s; Pq = g_p1q; }
    else           { X = x2; Nrm = g_n2; Xh = g_x2h; blk -= 256; Ps = g_p2s; Pq = g_p2q; }
    int row0 = blk * 16 + warp * 2;
    const float4* p0 = (const float4*)(X + row0 * DIM);
    const float4* p1 = (const float4*)(X + (row0 + 1) * DIM);
    // 4 loads up front: MLP 4
    float4 a0 = p0[lane];
    float4 a1 = p0[lane + 32];
    float4 c0 = p1[lane];
    float4 c1 = p1[lane + 32];
    // convert + store both rows
    {
        __half2 h0 = __floats2half2_rn(a0.x, a0.y), h1 = __floats2half2_rn(a0.z, a0.w);
        __half2 h2 = __floats2half2_rn(a1.x, a1.y), h3 = __floats2half2_rn(a1.z, a1.w);
        uint2* d0 = (uint2*)(Xh + row0 * DIM);
        d0[lane]      = make_uint2(*(uint32_t*)&h0, *(uint32_t*)&h1);
        d0[lane + 32] = make_uint2(*(uint32_t*)&h2, *(uint32_t*)&h3);
        __half2 g0 = __floats2half2_rn(c0.x, c0.y), g1 = __floats2half2_rn(c0.z, c0.w);
        __half2 g2 = __floats2half2_rn(c1.x, c1.y), g3 = __floats2half2_rn(c1.z, c1.w);
        uint2* d1 = (uint2*)(Xh + (row0 + 1) * DIM);
        d1[lane]      = make_uint2(*(uint32_t*)&g0, *(uint32_t*)&g1);
        d1[lane + 32] = make_uint2(*(uint32_t*)&g2, *(uint32_t*)&g3);
    }
    float s0 = a0.x + a0.y + a0.z + a0.w + a1.x + a1.y + a1.z + a1.w;
    float q0 = a0.x*a0.x + a0.y*a0.y + a0.z*a0.z + a0.w*a0.w
             + a1.x*a1.x + a1.y*a1.y + a1.z*a1.z + a1.w*a1.w;
    float s1 = c0.x + c0.y + c0.z + c0.w + c1.x + c1.y + c1.z + c1.w;
    float q1 = c0.x*c0.x + c0.y*c0.y + c0.z*c0.z + c0.w*c0.w
             + c1.x*c1.x + c1.y*c1.y + c1.z*c1.z + c1.w*c1.w;
    // two interleaved shuffle trees (ILP 4 chains)
#pragma unroll
    for (int off = 16; off; off >>= 1) {
        s0 += __shfl_xor_sync(0xffffffffu, s0, off);
        q0 += __shfl_xor_sync(0xffffffffu, q0, off);
        s1 += __shfl_xor_sync(0xffffffffu, s1, off);
        q1 += __shfl_xor_sync(0xffffffffu, q1, off);
    }
    __shared__ float bs[8], bq[8];
    if (lane == 0) {
        Nrm[row0] = q0;
        Nrm[row0 + 1] = q1;
        bs[warp] = s0 + s1;
        bq[warp] = q0 + q1;
    }
    __syncthreads();
    if (t == 0) {
        float S = 0.f, Q = 0.f;
#pragma unroll
        for (int w = 0; w < 8; w++) { S += bs[w]; Q += bq[w]; }
        Ps[blk] = S;
        Pq[blk] = Q;
    }
}

// ---------------------------------------------------------------------------
// k_att: heterogeneous launch, grid 128 x 512 threads.
//  CTAs [0,64): FUSED attention + projection, 128-row tiles:
//    jb(2) x (b*2+which)(32). 16 warps, warp tile 64x32.
//  CTAs [64,128): BN-apply for channels 0/2 (depends only on k_prep).
// ---------------------------------------------------------------------------
__global__ void __launch_bounds__(512, 1) k_att(const float* __restrict__ x1,
                                                const float* __restrict__ x2,
                                                const float* __restrict__ gamma,
                                                const float* __restrict__ beta,
                                                float* __restrict__ outp) {
    extern __shared__ char smem[];
    uint32_t sb = smem_to_u32(smem);
    int t = threadIdx.x, lane = t & 31, wid = t >> 5;

    if (blockIdx.x >= 64) {
        // ===== bn02 path: unit = (which, bb, half-32K) =====
        int u = blockIdx.x - 64;            // 0..63
        int unit = u >> 1, half = u & 1;
        int which = unit >> 4, bb = unit & 15;
        const float* src = which ? x2 : x1;
        const float* Ps = which ? g_p2s : g_p1s;
        const float* Pq = which ? g_p2q : g_p1q;
        __shared__ float rs[256], rq[256];
        if (t < 256) { rs[t] = Ps[t]; rq[t] = Pq[t]; }
        __syncthreads();
#pragma unroll
        for (int off = 128; off; off >>= 1) {
            if (t < off) { rs[t] += rs[t + off]; rq[t] += rq[t + off]; }
            __syncthreads();
        }
        const float Ninv = 1.0f / (float)NTOT;
        float mean = rs[0] * Ninv;
        float var = rq[0] * Ninv - mean * mean;
        float sc = gamma[0] * rsqrtf(var + 1e-5f);
        float sh = beta[0] - mean * sc;
        int e0 = (which << 21) + (bb << 17) + half * 32768;
        const float4* s4 = (const float4*)&src[bb * MAT + half * 32768];
        float4* o4 = (float4*)&outp[e0];
#pragma unroll
        for (int g = 0; g < 2; g++) {
            float4 v[8];
#pragma unroll
            for (int i = 0; i < 8; i++) v[i] = s4[t + (g * 8 + i) * 512];
#pragma unroll
            for (int i = 0; i < 8; i++) {
                float4 o;
                o.x = v[i].x * sc + sh;
                o.y = v[i].y * sc + sh;
                o.z = v[i].z * sc + sh;
                o.w = v[i].w * sc + sh;
                o4[t + (g * 8 + i) * 512] = o;
            }
        }
        return;
    }

    // ===== att path: 64 tiles = jb(2) x (b*2+which)(32) =====
    float* snc   = (float*)(smem + OFF_SNC);
    float* snr   = (float*)(smem + OFF_SNR);
    float* scorr = (float*)(smem + OFF_CORR);
    int jb = blockIdx.x & 1;
    int bz = blockIdx.x >> 1;            // 0..31
    int b = bz >> 1, which = bz & 1;

    const __half* R = (which ? g_x1h : g_x2h) + b * MAT + jb * 128 * DIM;
    const __half* C = (which ? g_x2h : g_x1h) + b * MAT;
    const float* NR = (which ? g_n1 : g_n2) + b * SEQ + jb * 128;
    const float* NC = (which ? g_n2 : g_n1) + b * SEQ;
    float* out = (which ? g_x1att : g_x2att) + b * MAT + jb * 128 * DIM;

    if (t < 256) { snc[t] = NC[t]; scorr[t] = g_corr[t]; }
    else if (t < 384) snr[t - 256] = NR[t - 256];

    const uint32_t sR  = sb + OFF_SR;
    const uint32_t sAt = sb + OFF_SAT;
    const uint32_t sD  = sb + OFF_SD;

    auto loadB = [&](const __half* src, int kc, int buf) {
#pragma unroll
        for (int s = 0; s < 4; s++) {
            int seg = t + s * 512;
            int row = seg >> 3, c = seg & 7;
            cp16(sD + (uint32_t)(buf * BTILE + row * PB + c * 16),
                 src + row * SEQ + kc * 64 + c * 8);
        }
    };

    // R strip [128][256]: 4096 cp16
#pragma unroll
    for (int s = 0; s < 8; s++) {
        int seg = t + s * 512;
        int row = seg >> 5, c = seg & 31;
        cp16(sR + (uint32_t)(row * PR + c * 16), R + row * DIM + c * 8);
    }
    loadB(C, 0, 0);
    CP_COMMIT();

    int m0 = (wid & 1) * 64, n0 = (wid >> 1) * 32;
    float acc[4][4][4] = {};

    // ---- stage 1 ----
    for (int kc = 0; kc < 4; kc++) {
        if (kc < 3) loadB(C, kc + 1, (kc + 1) & 1);
        else        loadB(g_Wh, 0, 0);          // prefetch W chunk 0
        CP_COMMIT();
        CP_WAIT1();
        __syncthreads();
        uint32_t bufB = sD + (kc & 1) * BTILE;
#pragma unroll
        for (int kk = 0; kk < 4; kk++) {
            uint32_t af[4][4];
#pragma unroll
            for (int mi = 0; mi < 4; mi++)
                ldsm4(af[mi], sR + (uint32_t)((m0 + mi * 16 + (lane & 15)) * PR
                                              + kc * 128 + kk * 32 + (lane >> 4) * 16));
            uint32_t bf[4][2];
#pragma unroll
            for (int np = 0; np < 2; np++) {
                uint32_t r[4];
                ldsm4(r, bufB + (uint32_t)((n0 + np * 16 + (lane & 7) + ((lane >> 4) & 1) * 8) * PB
                                            + kk * 32 + ((lane >> 3) & 1) * 16));
                bf[np * 2][0] = r[0]; bf[np * 2][1] = r[1];
                bf[np * 2 + 1][0] = r[2]; bf[np * 2 + 1][1] = r[3];
            }
#pragma unroll
            for (int mi = 0; mi < 4; mi++)
#pragma unroll
                for (int ni = 0; ni < 4; ni++)
                    mma_fp16(acc[mi][ni], af[mi], bf[ni]);
        }
        __syncthreads();
    }

    // ---- stage-1 epilogue: delta -> sAt, reset acc ----
#pragma unroll
    for (int mi = 0; mi < 4; mi++) {
#pragma unroll
        for (int ni = 0; ni < 4; ni++) {
#pragma unroll
            for (int h = 0; h < 2; h++) {
                int row = m0 + mi * 16 + (lane >> 2) + h * 8;
                int col = n0 + ni * 8 + (lane & 3) * 2;
                float e0 = fmaxf(snr[row] + snc[col]     - 2.f * acc[mi][ni][h * 2],     0.f);
                float e1 = fmaxf(snr[row] + snc[col + 1] - 2.f * acc[mi][ni][h * 2 + 1], 0.f);
                float a0 = 1.f / (sqrtf(e0 + 1e-6f) + 1.f) - ABAR;
                float a1 = 1.f / (sqrtf(e1 + 1e-6f) + 1.f) - ABAR;
                *(__half2*)(smem + OFF_SAT + row * PR + col * 2) = __floats2half2_rn(a0, a1);
                acc[mi][ni][h * 2] = 0.f;
                acc[mi][ni][h * 2 + 1] = 0.f;
            }
        }
    }
    __syncthreads();

    // ---- stage 2 ----
    for (int kc = 0; kc < 4; kc++) {
        if (kc < 3) loadB(g_Wh, kc + 1, (kc + 1) & 1);
        CP_COMMIT();
        if (kc < 3) CP_WAIT1(); else CP_WAIT0();
        __syncthreads();
        uint32_t bufB = sD + (kc & 1) * BTILE;
#pragma unroll
        for (int kk = 0; kk < 4; kk++) {
            uint32_t af[4][4];
#pragma unroll
            for (int mi = 0; mi < 4; mi++)
                ldsm4(af[mi], sAt + (uint32_t)((m0 + mi * 16 + (lane & 15)) * PR
                                               + kc * 128 + kk * 32 + (lane >> 4) * 16));
            uint32_t bf[4][2];
#pragma unroll
            for (int np = 0; np < 2; np++) {
                uint32_t r[4];
                ldsm4(r, bufB + (uint32_t)((n0 + np * 16 + (lane & 7) + ((lane >> 4) & 1) * 8) * PB
                                            + kk * 32 + ((lane >> 3) & 1) * 16));
                bf[np * 2][0] = r[0]; bf[np * 2][1] = r[1];
                bf[np * 2 + 1][0] = r[2]; bf[np * 2 + 1][1] = r[3];
            }
#pragma unroll
            for (int mi = 0; mi < 4; mi++)
#pragma unroll
                for (int ni = 0; ni < 4; ni++)
                    mma_fp16(acc[mi][ni], af[mi], bf[ni]);
        }
        __syncthreads();
    }

    // ---- stage-2 epilogue: +corr, fp32 store, partial BN stats ----
    float ps = 0.f, pq = 0.f;
#pragma unroll
    for (int mi = 0; mi < 4; mi++) {
#pragma unroll
        for (int ni = 0; ni < 4; ni++) {
#pragma unroll
            for (int h = 0; h < 2; h++) {
                int row = m0 + mi * 16 + (lane >> 2) + h * 8;
                int col = n0 + ni * 8 + (lane & 3) * 2;
                float v0 = acc[mi][ni][h * 2]     + scorr[col];
                float v1 = acc[mi][ni][h * 2 + 1] + scorr[col + 1];
                *(float2*)&out[row * DIM + col] = make_float2(v0, v1);
                ps += v0 + v1;
                pq += v0 * v0 + v1 * v1;
            }
        }
    }
#pragma unroll
    for (int off = 16; off; off >>= 1) {
        ps += __shfl_xor_sync(0xffffffffu, ps, off);
        pq += __shfl_xor_sync(0xffffffffu, pq, off);
    }
    float* ws = (float*)(smem + OFF_STAT);
    float* wq = ws + 16;
    if (lane == 0) { ws[wid] = ps; wq[wid] = pq; }
    __syncthreads();
    if (t == 0) {
        float S = 0.f, Q = 0.f;
#pragma unroll
        for (int w = 0; w < 16; w++) { S += ws[w]; Q += wq[w]; }
        int slot = b * 2 + jb;
        if (which) { g_pa1s[slot] = S; g_pa1q[slot] = Q; }
        else       { g_pa3s[slot] = S; g_pa3q[slot] = Q; }
    }
}

// ---------------------------------------------------------------------------
// k_bn13: BN-apply for channels 1/3 (att half of output, 16MB).
// grid 256 x 256: block = (which, bb, chunk of 8192 in c=1 plane).
// ---------------------------------------------------------------------------
__global__ void __launch_bounds__(256) k_bn13(const float* __restrict__ gamma,
                                              const float* __restrict__ beta,
                                              float* __restrict__ outp) {
    int t = threadIdx.x;
    int u = blockIdx.x;                  // 0..255
    int which = u >> 7;
    int bb = (u >> 3) & 15;
    int chunk = u & 7;
    const float* src = which ? g_x2att : g_x1att;
    const float* Ps = which ? g_pa3s : g_pa1s;
    const float* Pq = which ? g_pa3q : g_pa1q;

    __shared__ float rs[32], rq[32];
    if (t < 32) { rs[t] = Ps[t]; rq[t] = Pq[t]; }
    __syncthreads();
#pragma unroll
    for (int off = 16; off; off >>= 1) {
        if (t < off) { rs[t] += rs[t + off]; rq[t] += rq[t + off]; }
        __syncthreads();
    }
    const float Ninv = 1.0f / (float)NTOT;
    float mean = rs[0] * Ninv;
    float var = rq[0] * Ninv - mean * mean;
    float sc = gamma[1] * rsqrtf(var + 1e-5f);
    float sh = beta[1] - mean * sc;

    int pos = chunk * 8192;
    int e0 = (which << 21) + (bb << 17) + 65536 + pos;
    const float4* s4 = (const float4*)&src[bb * MAT + pos];
    float4* o4 = (float4*)&outp[e0];
    float4 v[8];
#pragma unroll
    for (int i = 0; i < 8; i++) v[i] = s4[t + i * 256];
#pragma unroll
    for (int i = 0; i < 8; i++) {
        float4 o;
        o.x = v[i].x * sc + sh;
        o.y = v[i].y * sc + sh;
        o.z = v[i].z * sc + sh;
        o.w = v[i].w * sc + sh;
        o4[t + i * 256] = o;
    }
}

// ---------------------------------------------------------------------------
extern "C" void kernel_launch(void* const* d_in, const int* in_sizes, int n_in,
                              void* d_out, int out_size) {
    const float* x1    = (const float*)d_in[0];
    const float* x2    = (const float*)d_in[1];
    const float* W     = (const float*)d_in[2];
    const float* bias  = (const float*)d_in[3];
    const float* gamma = (const float*)d_in[4];
    const float* beta  = (const float*)d_in[5];
    float* out = (float*)d_out;

    cudaFuncSetAttribute(k_att, cudaFuncAttributeMaxDynamicSharedMemorySize, F_SMEM);

    k_prep<<<608, 256>>>(x1, x2, W, bias);
    k_att<<<128, 512, F_SMEM>>>(x1, x2, gamma, beta, out);
    k_bn13<<<256, 256>>>(gamma, beta, out);
}

// round 14
// speedup vs baseline: 1.3257x; 1.3257x over previous
#include <cuda_runtime.h>
#include <cuda_fp16.h>
#include <stdint.h>

#define BATCH 16
#define SEQ 256
#define DIM 256
#define MAT 65536
#define NTOT 1048576
#define ABAR 0.042323627f   // 1/(1+sqrt(512))

// ---------------------------------------------------------------------------
// Device-global scratch (no atomics: fixed-slot partial sums)
// ---------------------------------------------------------------------------
__device__ float g_x1att[NTOT];
__device__ float g_x2att[NTOT];
__device__ float g_n1[BATCH*SEQ];
__device__ float g_n2[BATCH*SEQ];
__device__ float g_corr[DIM];  // ABAR*rowsum(W)+bias
__device__ __half g_x1h[NTOT];
__device__ __half g_x2h[NTOT];
__device__ __half g_Wh[SEQ*DIM];
// partial BN stats
__device__ float g_p1s[512], g_p1q[512];   // x1 (ch0), one per prep block
__device__ float g_p2s[512], g_p2q[512];   // x2 (ch2)
__device__ float g_pa1s[64], g_pa1q[64];   // x1_att (ch1), one per att CTA
__device__ float g_pa3s[64], g_pa3q[64];   // x2_att (ch3)

// ---------------------------------------------------------------------------
// Portable-ISA helpers (sm_80+)
// ---------------------------------------------------------------------------
__device__ __forceinline__ uint32_t smem_to_u32(const void* p) {
    uint32_t a;
    asm("{ .reg .u64 t; cvta.to.shared.u64 t, %1; cvt.u32.u64 %0, t; }" : "=r"(a) : "l"(p));
    return a;
}
__device__ __forceinline__ void ldsm4(uint32_t* r, uint32_t addr) {
    asm volatile("ldmatrix.sync.aligned.m8n8.x4.shared.b16 {%0,%1,%2,%3}, [%4];"
                 : "=r"(r[0]), "=r"(r[1]), "=r"(r[2]), "=r"(r[3]) : "r"(addr));
}
__device__ __forceinline__ void mma_fp16(float* c, const uint32_t* a, const uint32_t* b) {
    asm volatile("mma.sync.aligned.m16n8k16.row.col.f32.f16.f16.f32 "
                 "{%0,%1,%2,%3}, {%4,%5,%6,%7}, {%8,%9}, {%0,%1,%2,%3};"
                 : "+f"(c[0]), "+f"(c[1]), "+f"(c[2]), "+f"(c[3])
                 : "r"(a[0]), "r"(a[1]), "r"(a[2]), "r"(a[3]), "r"(b[0]), "r"(b[1]));
}
__device__ __forceinline__ void cp16(uint32_t saddr, const void* g) {
    asm volatile("cp.async.cg.shared.global [%0], [%1], 16;" :: "r"(saddr), "l"(g));
}
#define CP_COMMIT() asm volatile("cp.async.commit_group;" ::: "memory")
#define CP_WAIT1()  asm volatile("cp.async.wait_group 1;" ::: "memory")
#define CP_WAIT0()  asm volatile("cp.async.wait_group 0;" ::: "memory")

// SMEM geometry (64-row tiles, 128-wide K chunks)
#define PR 528                  // pitch of 256-half rows (conflict-free)
#define PB2 272                 // pitch of 128-half rows (272/4 mod 32 = 4)
#define BTILE2 (256 * PB2)      // 69632: one B chunk [256 n][128 k]
#define OFF_SNC   0             // 256 floats
#define OFF_SNR   1024          // 64 floats
#define OFF_CORR  1280          // 256 floats
#define OFF_STAT  2304          // 32 floats
#define OFF_SR    2432          // 64 x PR = 33792
#define OFF_SAT   36224         // 64 x PR = 33792
#define OFF_SD    70016         // 2 x BTILE2 = 139264
#define F_SMEM    209280

// ---------------------------------------------------------------------------
// k_prep (R9/R12 form): blocks [0,512) x1: norms+partial stats+fp16.
//   [512,1024) x2.  [1024,1088) W fp16.  [1088,1120) corr.
// ---------------------------------------------------------------------------
__global__ void __launch_bounds__(256) k_prep(const float* __restrict__ x1,
                                              const float* __restrict__ x2,
                                              const float* __restrict__ W,
                                              const float* __restrict__ bias) {
    int blk = blockIdx.x;
    int t = threadIdx.x;
    if (blk >= 1088) {   // corr rows
        int warp = t >> 5, lane = t & 31;
        int o = (blk - 1088) * 8 + warp;
        float s = 0.f;
#pragma unroll
        for (int c = 0; c < 8; c++) s += W[o * SEQ + lane + c * 32];
#pragma unroll
        for (int off = 16; off; off >>= 1) s += __shfl_xor_sync(0xffffffffu, s, off);
        if (lane == 0) g_corr[o] = ABAR * s + bias[o];
        return;
    }
    if (blk >= 1024) {   // W fp16 (vectorized)
        int base = (blk - 1024) * 1024 + t * 4;
        float4 v = *(const float4*)&W[base];
        __half2 h0 = __floats2half2_rn(v.x, v.y);
        __half2 h1 = __floats2half2_rn(v.z, v.w);
        *(uint2*)&g_Wh[base] = make_uint2(*(uint32_t*)&h0, *(uint32_t*)&h1);
        return;
    }
    const float* X;
    float* Nrm;
    __half* Xh;
    float* Ps;
    float* Pq;
    if (blk < 512) { X = x1; Nrm = g_n1; Xh = g_x1h; Ps = g_p1s; Pq = g_p1q; }
    else           { X = x2; Nrm = g_n2; Xh = g_x2h; blk -= 512; Ps = g_p2s; Pq = g_p2q; }
    int warp = t >> 5, lane = t & 31;
    int row = blk * 8 + warp;
    const float4* p4 = (const float4*)(X + row * DIM);
    float4 v0 = p4[lane];
    float4 v1 = p4[lane + 32];
    float s = v0.x + v0.y + v0.z + v0.w + v1.x + v1.y + v1.z + v1.w;
    float q = v0.x*v0.x + v0.y*v0.y + v0.z*v0.z + v0.w*v0.w
            + v1.x*v1.x + v1.y*v1.y + v1.z*v1.z + v1.w*v1.w;
    {
        __half2 a0 = __floats2half2_rn(v0.x, v0.y);
        __half2 a1 = __floats2half2_rn(v0.z, v0.w);
        __half2 b0 = __floats2half2_rn(v1.x, v1.y);
        __half2 b1 = __floats2half2_rn(v1.z, v1.w);
        uint2* dst = (uint2*)(Xh + row * DIM);
        dst[lane]      = make_uint2(*(uint32_t*)&a0, *(uint32_t*)&a1);
        dst[lane + 32] = make_uint2(*(uint32_t*)&b0, *(uint32_t*)&b1);
    }
#pragma unroll
    for (int off = 16; off; off >>= 1) {
        s += __shfl_xor_sync(0xffffffffu, s, off);
        q += __shfl_xor_sync(0xffffffffu, q, off);
    }
    __shared__ float bs[8], bq[8];
    if (lane == 0) { Nrm[row] = q; bs[warp] = s; bq[warp] = q; }
    __syncthreads();
    if (t == 0) {
        float S = 0.f, Q = 0.f;
#pragma unroll
        for (int w = 0; w < 8; w++) { S += bs[w]; Q += bq[w]; }
        Ps[blk] = S;
        Pq[blk] = Q;
    }
}

// ---------------------------------------------------------------------------
// k_att: heterogeneous launch, grid 192 x 512 threads.
//  CTAs [0,128): FUSED attention + projection, 64-row tiles:
//    jb(4) x (b*2+which)(32). 16 warps, warp tile 32x32.
//    K pipeline: 2 chunks of 128 per stage (half the barriers of R12).
//  CTAs [128,192): BN-apply for channels 0/2 (depends only on k_prep).
// ---------------------------------------------------------------------------
__global__ void __launch_bounds__(512, 1) k_att(const float* __restrict__ x1,
                                                const float* __restrict__ x2,
                                                const float* __restrict__ gamma,
                                                const float* __restrict__ beta,
                                                float* __restrict__ outp) {
    extern __shared__ char smem[];
    uint32_t sb = smem_to_u32(smem);
    int t = threadIdx.x, lane = t & 31, wid = t >> 5;

    if (blockIdx.x >= 128) {
        // ===== bn02 path: unit = (which, bb, half-32K) =====
        int u = blockIdx.x - 128;           // 0..63
        int unit = u >> 1, half = u & 1;
        int which = unit >> 4, bb = unit & 15;
        const float* src = which ? x2 : x1;
        const float* Ps = which ? g_p2s : g_p1s;
        const float* Pq = which ? g_p2q : g_p1q;
        __shared__ float rs[512], rq[512];
        rs[t] = Ps[t]; rq[t] = Pq[t];
        __syncthreads();
#pragma unroll
        for (int off = 256; off; off >>= 1) {
            if (t < off) { rs[t] += rs[t + off]; rq[t] += rq[t + off]; }
            __syncthreads();
        }
        const float Ninv = 1.0f / (float)NTOT;
        float mean = rs[0] * Ninv;
        float var = rq[0] * Ninv - mean * mean;
        float sc = gamma[0] * rsqrtf(var + 1e-5f);
        float sh = beta[0] - mean * sc;
        int e0 = (which << 21) + (bb << 17) + half * 32768;
        const float4* s4 = (const float4*)&src[bb * MAT + half * 32768];
        float4* o4 = (float4*)&outp[e0];
#pragma unroll
        for (int g = 0; g < 2; g++) {
            float4 v[8];
#pragma unroll
            for (int i = 0; i < 8; i++) v[i] = s4[t + (g * 8 + i) * 512];
#pragma unroll
            for (int i = 0; i < 8; i++) {
                float4 o;
                o.x = v[i].x * sc + sh;
                o.y = v[i].y * sc + sh;
                o.z = v[i].z * sc + sh;
                o.w = v[i].w * sc + sh;
                o4[t + (g * 8 + i) * 512] = o;
            }
        }
        return;
    }

    // ===== att path: 128 tiles = jb(4) x (b*2+which)(32) =====
    float* snc   = (float*)(smem + OFF_SNC);
    float* snr   = (float*)(smem + OFF_SNR);
    float* scorr = (float*)(smem + OFF_CORR);
    int jb = blockIdx.x & 3;
    int bz = blockIdx.x >> 2;            // 0..31
    int b = bz >> 1, which = bz & 1;

    const __half* R = (which ? g_x1h : g_x2h) + b * MAT + jb * 64 * DIM;
    const __half* C = (which ? g_x2h : g_x1h) + b * MAT;
    const float* NR = (which ? g_n1 : g_n2) + b * SEQ + jb * 64;
    const float* NC = (which ? g_n2 : g_n1) + b * SEQ;
    float* out = (which ? g_x1att : g_x2att) + b * MAT + jb * 64 * DIM;

    if (t < 256) { snc[t] = NC[t]; scorr[t] = g_corr[t]; }
    else if (t < 320) snr[t - 256] = NR[t - 256];

    const uint32_t sR  = sb + OFF_SR;
    const uint32_t sAt = sb + OFF_SAT;
    const uint32_t sD  = sb + OFF_SD;

    // B-chunk loader: [256 n][128 k] (64KB, 4096 cp16 = 8/thread)
    auto loadB = [&](const __half* src, int kc, int buf) {
#pragma unroll
        for (int s = 0; s < 8; s++) {
            int seg = t + s * 512;
            int row = seg >> 4, c = seg & 15;
            cp16(sD + (uint32_t)(buf * BTILE2 + row * PB2 + c * 16),
                 src + row * SEQ + kc * 128 + c * 8);
        }
    };

    // R strip [64][256]: 2048 cp16
#pragma unroll
    for (int s = 0; s < 4; s++) {
        int seg = t + s * 512;
        int row = seg >> 5, c = seg & 31;
        cp16(sR + (uint32_t)(row * PR + c * 16), R + row * DIM + c * 8);
    }
    loadB(C, 0, 0);
    CP_COMMIT();

    int m0 = (wid & 1) * 32, n0 = (wid >> 1) * 32;
    float acc[2][4][4] = {};

    // ---- stage 1: 2 K-chunks of 128 over dim ----
    for (int kc = 0; kc < 2; kc++) {
        if (kc < 1) loadB(C, 1, 1);
        else        loadB(g_Wh, 0, 0);          // prefetch W chunk 0
        CP_COMMIT();
        CP_WAIT1();
        __syncthreads();
        uint32_t bufB = sD + (kc & 1) * BTILE2;
#pragma unroll
        for (int kk = 0; kk < 8; kk++) {
            uint32_t af[2][4];
#pragma unroll
            for (int mi = 0; mi < 2; mi++)
                ldsm4(af[mi], sR + (uint32_t)((m0 + mi * 16 + (lane & 15)) * PR
                                              + kc * 256 + kk * 32 + (lane >> 4) * 16));
            uint32_t bf[4][2];
#pragma unroll
            for (int np = 0; np < 2; np++) {
                uint32_t r[4];
                ldsm4(r, bufB + (uint32_t)((n0 + np * 16 + (lane & 7) + ((lane >> 4) & 1) * 8) * PB2
                                            + kk * 32 + ((lane >> 3) & 1) * 16));
                bf[np * 2][0] = r[0]; bf[np * 2][1] = r[1];
                bf[np * 2 + 1][0] = r[2]; bf[np * 2 + 1][1] = r[3];
            }
#pragma unroll
            for (int mi = 0; mi < 2; mi++)
#pragma unroll
                for (int ni = 0; ni < 4; ni++)
                    mma_fp16(acc[mi][ni], af[mi], bf[ni]);
        }
        __syncthreads();
    }

    // ---- stage-1 epilogue: delta -> sAt, reset acc ----
#pragma unroll
    for (int mi = 0; mi < 2; mi++) {
#pragma unroll
        for (int ni = 0; ni < 4; ni++) {
#pragma unroll
            for (int h = 0; h < 2; h++) {
                int row = m0 + mi * 16 + (lane >> 2) + h * 8;
                int col = n0 + ni * 8 + (lane & 3) * 2;
                float e0 = fmaxf(snr[row] + snc[col]     - 2.f * acc[mi][ni][h * 2],     0.f);
                float e1 = fmaxf(snr[row] + snc[col + 1] - 2.f * acc[mi][ni][h * 2 + 1], 0.f);
                float a0 = 1.f / (sqrtf(e0 + 1e-6f) + 1.f) - ABAR;
                float a1 = 1.f / (sqrtf(e1 + 1e-6f) + 1.f) - ABAR;
                *(__half2*)(smem + OFF_SAT + row * PR + col * 2) = __floats2half2_rn(a0, a1);
                acc[mi][ni][h * 2] = 0.f;
                acc[mi][ni][h * 2 + 1] = 0.f;
            }
        }
    }
    __syncthreads();

    // ---- stage 2: 2 K-chunks of 128 over i (A = sAt, B = W chunks) ----
    for (int kc = 0; kc < 2; kc++) {
        if (kc < 1) loadB(g_Wh, 1, 1);
        CP_COMMIT();
        if (kc < 1) CP_WAIT1(); else CP_WAIT0();
        __syncthreads();
        uint32_t bufB = sD + (kc & 1) * BTILE2;
#pragma unroll
        for (int kk = 0; kk < 8; kk++) {
            uint32_t af[2][4];
#pragma unroll
            for (int mi = 0; mi < 2; mi++)
                ldsm4(af[mi], sAt + (uint32_t)((m0 + mi * 16 + (lane & 15)) * PR
                                               + kc * 256 + kk * 32 + (lane >> 4) * 16));
            uint32_t bf[4][2];
#pragma unroll
            for (int np = 0; np < 2; np++) {
                uint32_t r[4];
                ldsm4(r, bufB + (uint32_t)((n0 + np * 16 + (lane & 7) + ((lane >> 4) & 1) * 8) * PB2
                                            + kk * 32 + ((lane >> 3) & 1) * 16));
                bf[np * 2][0] = r[0]; bf[np * 2][1] = r[1];
                bf[np * 2 + 1][0] = r[2]; bf[np * 2 + 1][1] = r[3];
            }
#pragma unroll
            for (int mi = 0; mi < 2; mi++)
#pragma unroll
                for (int ni = 0; ni < 4; ni++)
                    mma_fp16(acc[mi][ni], af[mi], bf[ni]);
        }
        __syncthreads();
    }

    // ---- stage-2 epilogue: +corr, fp32 store, partial BN stats ----
    float ps = 0.f, pq = 0.f;
#pragma unroll
    for (int mi = 0; mi < 2; mi++) {
#pragma unroll
        for (int ni = 0; ni < 4; ni++) {
#pragma unroll
            for (int h = 0; h < 2; h++) {
                int row = m0 + mi * 16 + (lane >> 2) + h * 8;
                int col = n0 + ni * 8 + (lane & 3) * 2;
                float v0 = acc[mi][ni][h * 2]     + scorr[col];
                float v1 = acc[mi][ni][h * 2 + 1] + scorr[col + 1];
                *(float2*)&out[row * DIM + col] = make_float2(v0, v1);
                ps += v0 + v1;
                pq += v0 * v0 + v1 * v1;
            }
        }
    }
#pragma unroll
    for (int off = 16; off; off >>= 1) {
        ps += __shfl_xor_sync(0xffffffffu, ps, off);
        pq += __shfl_xor_sync(0xffffffffu, pq, off);
    }
    float* ws = (float*)(smem + OFF_STAT);
    float* wq = ws + 16;
    if (lane == 0) { ws[wid] = ps; wq[wid] = pq; }
    __syncthreads();
    if (t == 0) {
        float S = 0.f, Q = 0.f;
#pragma unroll
        for (int w = 0; w < 16; w++) { S += ws[w]; Q += wq[w]; }
        int slot = b * 4 + jb;
        if (which) { g_pa1s[slot] = S; g_pa1q[slot] = Q; }
        else       { g_pa3s[slot] = S; g_pa3q[slot] = Q; }
    }
}

// ---------------------------------------------------------------------------
// k_bn13: BN-apply for channels 1/3 (att half of output, 16MB).
// grid 256 x 256: block = (which, bb, chunk of 8192 in c=1 plane).
// ---------------------------------------------------------------------------
__global__ void __launch_bounds__(256) k_bn13(const float* __restrict__ gamma,
                                              const float* __restrict__ beta,
                                              float* __restrict__ outp) {
    int t = threadIdx.x;
    int u = blockIdx.x;                  // 0..255
    int which = u >> 7;
    int bb = (u >> 3) & 15;
    int chunk = u & 7;
    const float* src = which ? g_x2att : g_x1att;
    const float* Ps = which ? g_pa3s : g_pa1s;
    const float* Pq = which ? g_pa3q : g_pa1q;

    __shared__ float rs[64], rq[64];
    if (t < 64) { rs[t] = Ps[t]; rq[t] = Pq[t]; }
    __syncthreads();
#pragma unroll
    for (int off = 32; off; off >>= 1) {
        if (t < off) { rs[t] += rs[t + off]; rq[t] += rq[t + off]; }
        __syncthreads();
    }
    const float Ninv = 1.0f / (float)NTOT;
    float mean = rs[0] * Ninv;
    float var = rq[0] * Ninv - mean * mean;
    float sc = gamma[1] * rsqrtf(var + 1e-5f);
    float sh = beta[1] - mean * sc;

    int pos = chunk * 8192;
    int e0 = (which << 21) + (bb << 17) + 65536 + pos;
    const float4* s4 = (const float4*)&src[bb * MAT + pos];
    float4* o4 = (float4*)&outp[e0];
    float4 v[8];
#pragma unroll
    for (int i = 0; i < 8; i++) v[i] = s4[t + i * 256];
#pragma unroll
    for (int i = 0; i < 8; i++) {
        float4 o;
        o.x = v[i].x * sc + sh;
        o.y = v[i].y * sc + sh;
        o.z = v[i].z * sc + sh;
        o.w = v[i].w * sc + sh;
        o4[t + i * 256] = o;
    }
}

// ---------------------------------------------------------------------------
extern "C" void kernel_launch(void* const* d_in, const int* in_sizes, int n_in,
                              void* d_out, int out_size) {
    const float* x1    = (const float*)d_in[0];
    const float* x2    = (const float*)d_in[1];
    const float* W     = (const float*)d_in[2];
    const float* bias  = (const float*)d_in[3];
    const float* gamma = (const float*)d_in[4];
    const float* beta  = (const float*)d_in[5];
    float* out = (float*)d_out;

    cudaFuncSetAttribute(k_att, cudaFuncAttributeMaxDynamicSharedMemorySize, F_SMEM);

    k_prep<<<1120, 256>>>(x1, x2, W, bias);
    k_att<<<192, 512, F_SMEM>>>(x1, x2, gamma, beta, out);
    k_bn13<<<256, 256>>>(gamma, beta, out);
}